// round 13
// baseline (speedup 1.0000x reference)
#include <cuda_runtime.h>
#include <cuda_bf16.h>
#include <stdint.h>

#define NTOK 4096
#define DMODEL 1024
#define HDIM 1024
#define MDIM 64
#define NEXP 8
#define HEXP 512
#define VOCAB 32000

// ---------------- device scratch (module-scope: allocation-free) -------------
__device__ __nv_bfloat16 g_xbf [NTOK*DMODEL];
__device__ __nv_bfloat16 g_spk [NTOK*HDIM];
__device__ __nv_bfloat16 g_moe [NTOK*HDIM];
__device__ __nv_bfloat16 g_decd[NTOK*DMODEL];
__device__ __nv_bfloat16 g_contbf[NTOK*MDIM];
__device__ __nv_bfloat16 g_eobf [NTOK*MDIM];
__device__ __nv_bfloat16 g_h1  [(size_t)NEXP*NTOK*HEXP];
__device__ float g_cont [NTOK*MDIM];
__device__ float g_eo   [(size_t)NEXP*NTOK*MDIM];
__device__ float g_wfull[NTOK*NEXP];
__device__ __nv_bfloat16 g_Wenc[DMODEL*HDIM];
__device__ __nv_bfloat16 g_Ws2c[HDIM*MDIM];
__device__ __nv_bfloat16 g_We1 [NEXP*MDIM*HEXP];
__device__ __nv_bfloat16 g_We2 [NEXP*HEXP*MDIM];
__device__ __nv_bfloat16 g_Wc2s[MDIM*HDIM];
__device__ __nv_bfloat16 g_Wdec[HDIM*DMODEL];
__device__ __nv_bfloat16 g_Wout[(size_t)DMODEL*VOCAB];
__device__ float g_cs_s2c[MDIM];
__device__ float g_cs_dec[DMODEL];
__device__ float g_cs_out[VOCAB];
__device__ int   g_is32;

__device__ __forceinline__ uint32_t smem_u32(const void* p){
    return (uint32_t)__cvta_generic_to_shared(p);
}

// ------------------------------ small kernels --------------------------------
__global__ void detect_kernel(const unsigned int* w){
    __shared__ int any;
    if (threadIdx.x == 0) any = 0;
    __syncthreads();
    int loc = 0;
    for (int i = 2*threadIdx.x + 1; i < 4096; i += 2*blockDim.x)
        if (w[i] != 0u) loc = 1;
    if (loc) atomicOr(&any, 1);
    __syncthreads();
    if (threadIdx.x == 0) g_is32 = any;
}

__global__ void gather_kernel(const void* idsRaw, const float4* __restrict__ emb4,
                              __nv_bfloat162* __restrict__ x2){
    int n = blockIdx.x;
    long long v = g_is32 ? (long long)((const int*)idsRaw)[n]
                         : ((const long long*)idsRaw)[n];
    const float4* src = emb4 + v * (DMODEL/4);
    __nv_bfloat162* dst = x2 + (long)n * (DMODEL/2);
    for (int d = threadIdx.x; d < DMODEL/4; d += blockDim.x){
        float4 t = src[d];
        dst[2*d]   = __floats2bfloat162_rn(t.x, t.y);
        dst[2*d+1] = __floats2bfloat162_rn(t.z, t.w);
    }
}

// vectorized fp32->bf16 (n must be divisible by 4)
__global__ void f2b4_kernel(const float4* __restrict__ s, __nv_bfloat162* __restrict__ d, int n4){
    int i = blockIdx.x * 256 + threadIdx.x;
    if (i < n4){
        float4 v = s[i];
        d[2*i]   = __floats2bfloat162_rn(v.x, v.y);
        d[2*i+1] = __floats2bfloat162_rn(v.z, v.w);
    }
}

// vectorized convert + column sums (cs pre-zeroed). Each thread: 4 consecutive
// columns. grid (ceil(N/4/256), SEGS). Ndim divisible by 4.
__global__ void wconv_cs4_kernel(const float* __restrict__ W, __nv_bfloat16* __restrict__ Wb,
                                 float* __restrict__ cs, int Kdim, int Ndim){
    int j4 = blockIdx.x * 256 + threadIdx.x;
    if (j4 * 4 >= Ndim) return;
    int j = j4 * 4;
    int seg = Kdim / gridDim.y;
    int k0 = blockIdx.y * seg;
    float s0 = 0.f, s1 = 0.f, s2 = 0.f, s3 = 0.f;
    for (int k = k0; k < k0 + seg; ++k){
        float4 v = *(const float4*)(W + (long)k * Ndim + j);
        s0 += v.x; s1 += v.y; s2 += v.z; s3 += v.w;
        __nv_bfloat162* o = (__nv_bfloat162*)(Wb + (long)k * Ndim + j);
        o[0] = __floats2bfloat162_rn(v.x, v.y);
        o[1] = __floats2bfloat162_rn(v.z, v.w);
    }
    atomicAdd(&cs[j],     s0);
    atomicAdd(&cs[j + 1], s1);
    atomicAdd(&cs[j + 2], s2);
    atomicAdd(&cs[j + 3], s3);
}

__global__ void router_kernel(const float* __restrict__ cont,
                              const float* __restrict__ rW1, const float* __restrict__ rb1,
                              const float* __restrict__ rW2, const float* __restrict__ rb2,
                              float* __restrict__ probs, float* __restrict__ wfull){
    int n = blockIdx.x * 8 + (threadIdx.x >> 5);
    int lane = threadIdx.x & 31;
    const float* cn = cont + (long)n * MDIM;
    float h0 = rb1[lane], h1 = rb1[lane + 32];
    #pragma unroll 8
    for (int k = 0; k < 64; ++k){
        float c = cn[k];
        h0 += c * rW1[k * 64 + lane];
        h1 += c * rW1[k * 64 + lane + 32];
    }
    h0 = tanhf(h0); h1 = tanhf(h1);
    float lg[8];
    #pragma unroll
    for (int e = 0; e < 8; ++e){
        float v = h0 * rW2[lane * 8 + e] + h1 * rW2[(lane + 32) * 8 + e];
        #pragma unroll
        for (int o = 16; o > 0; o >>= 1) v += __shfl_xor_sync(0xffffffffu, v, o);
        lg[e] = v + rb2[e];
    }
    float mx = lg[0];
    #pragma unroll
    for (int e = 1; e < 8; ++e) mx = fmaxf(mx, lg[e]);
    float se = 0.f;
    #pragma unroll
    for (int e = 0; e < 8; ++e){ lg[e] = expf(lg[e] - mx); se += lg[e]; }
    float inv = 1.f / se;
    #pragma unroll
    for (int e = 0; e < 8; ++e) lg[e] *= inv;
    int i1 = 0; float v1 = lg[0];
    #pragma unroll
    for (int e = 1; e < 8; ++e) if (lg[e] > v1){ v1 = lg[e]; i1 = e; }
    int i2 = -1; float v2 = -1.f;
    #pragma unroll
    for (int e = 0; e < 8; ++e) if (e != i1 && lg[e] > v2){ v2 = lg[e]; i2 = e; }
    float winv = 1.f / (v1 + v2);
    if (lane == 0){
        #pragma unroll
        for (int e = 0; e < 8; ++e){
            probs[(long)n * 8 + e] = lg[e];
            wfull[(long)n * 8 + e] = (e == i1) ? v1 * winv : (e == i2) ? v2 * winv : 0.f;
        }
    }
}

__global__ void combine_kernel(const float* __restrict__ eo, const float* __restrict__ wfull,
                               __nv_bfloat16* __restrict__ out){
    int idx = blockIdx.x * 256 + threadIdx.x;
    int n = idx >> 6, m = idx & 63;
    float s = 0.f;
    #pragma unroll
    for (int e = 0; e < 8; ++e)
        s += wfull[(long)n * 8 + e] * eo[((long)e * NTOK + n) * MDIM + m];
    out[idx] = __float2bfloat16(s);
}

// ---------------- BIG GEMM: BM=128 BN=128 BK=64, 256 threads -----------------
// C[4096 x N] = A[4096 x K] * B[K x N] (+bias +0.5*colsum); warp tile 64x32.
// EPI 0: f32 out ; 1: bf16 out = sigmoid(v)-0.5 = 0.5*tanh(v/2).
#define KBM 128
#define KBN 128
#define KBK 64
#define KST 3

template<int EPI>
__global__ void __launch_bounds__(256) gemm_bk64(
    const __nv_bfloat16* __restrict__ A, const __nv_bfloat16* __restrict__ B,
    void* __restrict__ C, const float* __restrict__ bias, const float* __restrict__ colsum,
    int Kdim, int Ndim)
{
    constexpr int ASTG = KBM * 128;
    constexpr int BSTG = KBK * 256;
    extern __shared__ char smem[];
    char* sA = smem;
    char* sB = smem + KST * ASTG;

    int tid = threadIdx.x, lane = tid & 31, wid = tid >> 5;
    int wm = wid >> 2, wn = wid & 3;
    int bm = blockIdx.y * KBM, bn = blockIdx.x * KBN;
    const int Kt = Kdim / KBK;

    auto load_stage = [&](int kt, int st){
        const __nv_bfloat16* Ag = A + (long)bm * Kdim + kt * KBK;
        #pragma unroll
        for (int i = 0; i < 4; ++i){
            int idx = tid + i * 256;
            int row = idx >> 3, g = idx & 7;
            uint32_t dst = smem_u32(sA + st * ASTG + row * 128 + ((g ^ (row & 7)) * 16));
            const void* src = Ag + (long)row * Kdim + g * 8;
            asm volatile("cp.async.cg.shared.global [%0],[%1],16;\n" :: "r"(dst), "l"(src));
        }
        const __nv_bfloat16* Bg = B + (long)(kt * KBK) * Ndim + bn;
        #pragma unroll
        for (int i = 0; i < 4; ++i){
            int idx = tid + i * 256;
            int k = idx >> 4, g = idx & 15;
            uint32_t dst = smem_u32(sB + st * BSTG + k * 256 + ((g ^ (k & 15)) * 16));
            const void* src = Bg + (long)k * Ndim + g * 8;
            asm volatile("cp.async.cg.shared.global [%0],[%1],16;\n" :: "r"(dst), "l"(src));
        }
    };

    float acc[4][4][4];
    #pragma unroll
    for (int i = 0; i < 4; ++i)
        #pragma unroll
        for (int j = 0; j < 4; ++j){ acc[i][j][0]=0.f; acc[i][j][1]=0.f; acc[i][j][2]=0.f; acc[i][j][3]=0.f; }

    load_stage(0, 0);
    asm volatile("cp.async.commit_group;\n");
    if (Kt > 1) load_stage(1, 1);
    asm volatile("cp.async.commit_group;\n");

    for (int kt = 0; kt < Kt; ++kt){
        asm volatile("cp.async.wait_group 1;\n");
        __syncthreads();
        int st = kt % KST;
        if (kt + 2 < Kt) load_stage(kt + 2, (kt + 2) % KST);
        asm volatile("cp.async.commit_group;\n");

        char* cA = sA + st * ASTG;
        char* cB = sB + st * BSTG;
        #pragma unroll
        for (int kk = 0; kk < 4; ++kk){
            uint32_t af[4][4];
            #pragma unroll
            for (int mf = 0; mf < 4; ++mf){
                int r = wm * 64 + mf * 16 + (lane & 15);
                int g = kk * 2 + (lane >> 4);
                uint32_t addr = smem_u32(cA + r * 128 + ((g ^ (r & 7)) * 16));
                asm volatile("ldmatrix.sync.aligned.m8n8.x4.shared.b16 {%0,%1,%2,%3},[%4];\n"
                    : "=r"(af[mf][0]), "=r"(af[mf][1]), "=r"(af[mf][2]), "=r"(af[mf][3]) : "r"(addr));
            }
            uint32_t bfr[4][2];
            #pragma unroll
            for (int n2 = 0; n2 < 2; ++n2){
                int k = kk * 16 + (lane & 15);
                int gn = wn * 4 + n2 * 2 + (lane >> 4);
                uint32_t addr = smem_u32(cB + k * 256 + ((gn ^ (k & 15)) * 16));
                uint32_t r0, r1, r2, r3;
                asm volatile("ldmatrix.sync.aligned.m8n8.x4.trans.shared.b16 {%0,%1,%2,%3},[%4];\n"
                    : "=r"(r0), "=r"(r1), "=r"(r2), "=r"(r3) : "r"(addr));
                bfr[n2*2][0]=r0; bfr[n2*2][1]=r1; bfr[n2*2+1][0]=r2; bfr[n2*2+1][1]=r3;
            }
            #pragma unroll
            for (int mf = 0; mf < 4; ++mf)
                #pragma unroll
                for (int nf = 0; nf < 4; ++nf)
                    asm volatile("mma.sync.aligned.m16n8k16.row.col.f32.bf16.bf16.f32 "
                        "{%0,%1,%2,%3},{%4,%5,%6,%7},{%8,%9},{%0,%1,%2,%3};\n"
                        : "+f"(acc[mf][nf][0]), "+f"(acc[mf][nf][1]),
                          "+f"(acc[mf][nf][2]), "+f"(acc[mf][nf][3])
                        : "r"(af[mf][0]), "r"(af[mf][1]), "r"(af[mf][2]), "r"(af[mf][3]),
                          "r"(bfr[nf][0]), "r"(bfr[nf][1]));
        }
    }

    #pragma unroll
    for (int mf = 0; mf < 4; ++mf)
        #pragma unroll
        for (int nf = 0; nf < 4; ++nf){
            int gm = bm + wm * 64 + mf * 16 + (lane >> 2);
            int cc = bn + wn * 32 + nf * 8 + (lane & 3) * 2;
            float b0 = bias ? bias[cc] : 0.f;
            float b1 = bias ? bias[cc + 1] : 0.f;
            if (colsum){ b0 += 0.5f * colsum[cc]; b1 += 0.5f * colsum[cc + 1]; }
            float v00 = acc[mf][nf][0] + b0, v01 = acc[mf][nf][1] + b1;
            float v10 = acc[mf][nf][2] + b0, v11 = acc[mf][nf][3] + b1;
            if (EPI == 0){
                float* Cp = (float*)C;
                *(float2*)(Cp + (long)gm * Ndim + cc)       = make_float2(v00, v01);
                *(float2*)(Cp + (long)(gm + 8) * Ndim + cc) = make_float2(v10, v11);
            } else {
                v00 = 0.5f * tanhf(0.5f * v00); v01 = 0.5f * tanhf(0.5f * v01);
                v10 = 0.5f * tanhf(0.5f * v10); v11 = 0.5f * tanhf(0.5f * v11);
                __nv_bfloat16* Cp = (__nv_bfloat16*)C;
                __nv_bfloat162 t0; t0.x = __float2bfloat16(v00); t0.y = __float2bfloat16(v01);
                __nv_bfloat162 t1; t1.x = __float2bfloat16(v10); t1.y = __float2bfloat16(v11);
                *(__nv_bfloat162*)(Cp + (long)gm * Ndim + cc)       = t0;
                *(__nv_bfloat162*)(Cp + (long)(gm + 8) * Ndim + cc) = t1;
            }
        }
}

// --------------------- small GEMM (proven path) ------------------------------
// EPI 0: f32 ; 2: relu bf16 ; 3: f32 to C AND plain bf16 to C2.
#define BM 128
#define BK 32
#define STAGES 3

template<int BN, int EPI>
__global__ void __launch_bounds__(256) gemm_bf16(
    const __nv_bfloat16* __restrict__ A, const __nv_bfloat16* __restrict__ B,
    void* __restrict__ C, const float* __restrict__ bias, const float* __restrict__ colsum,
    int Kdim, int Ndim, long aB, long bB, long cB, long biasB,
    __nv_bfloat16* __restrict__ C2)
{
    constexpr int WARPS_N = (BN == 128) ? 4 : 2;
    constexpr int WARPS_M = 8 / WARPS_N;
    constexpr int WMT = BM / WARPS_M;
    constexpr int WNT = BN / WARPS_N;
    constexpr int MF = WMT / 16;
    constexpr int NF = WNT / 8;
    constexpr int APITCH = 80;
    constexpr int ASTAGE = BM * APITCH;
    constexpr int BPITCH = BN * 2;
    constexpr int BSTAGE = BK * BPITCH;
    constexpr int GR = BN / 8;
    constexpr int BROWS = 256 / GR;
    constexpr int BPASSES = BK / BROWS;

    extern __shared__ char smem[];
    char* sA = smem;
    char* sB = smem + STAGES * ASTAGE;

    int z = blockIdx.z;
    A += z * aB; B += z * bB;
    const float* biasp = bias ? bias + z * biasB : nullptr;

    int tid = threadIdx.x, lane = tid & 31, wid = tid >> 5;
    int wm = wid / WARPS_N, wn = wid % WARPS_N;
    int bm = blockIdx.y * BM, bn = blockIdx.x * BN;
    int am = tid >> 2, ag = tid & 3;
    int bkr = tid / GR, bg = tid % GR;
    const int Ktiles = Kdim / BK;

    auto load_stage = [&](int kt, int st){
        const __nv_bfloat16* Ag = A + (long)bm * Kdim + kt * BK;
        #pragma unroll
        for (int p = 0; p < 2; ++p){
            int row = am + p * 64;
            uint32_t dst = smem_u32(sA + st * ASTAGE + row * APITCH + ag * 16);
            const void* src = Ag + (long)row * Kdim + ag * 8;
            asm volatile("cp.async.cg.shared.global [%0],[%1],16;\n" :: "r"(dst), "l"(src));
        }
        const __nv_bfloat16* Bg = B + (long)(kt * BK) * Ndim + bn;
        #pragma unroll
        for (int p = 0; p < BPASSES; ++p){
            int k = bkr + p * BROWS;
            uint32_t dst = smem_u32(sB + st * BSTAGE + k * BPITCH + ((bg ^ (k & 7)) * 16));
            const void* src = Bg + (long)k * Ndim + bg * 8;
            asm volatile("cp.async.cg.shared.global [%0],[%1],16;\n" :: "r"(dst), "l"(src));
        }
    };

    float acc[MF][NF][4];
    #pragma unroll
    for (int i = 0; i < MF; ++i)
        #pragma unroll
        for (int j = 0; j < NF; ++j){ acc[i][j][0]=0.f; acc[i][j][1]=0.f; acc[i][j][2]=0.f; acc[i][j][3]=0.f; }

    load_stage(0, 0);
    asm volatile("cp.async.commit_group;\n");
    if (Ktiles > 1) load_stage(1, 1);
    asm volatile("cp.async.commit_group;\n");

    for (int kt = 0; kt < Ktiles; ++kt){
        asm volatile("cp.async.wait_group 1;\n");
        __syncthreads();
        int st = kt % STAGES;
        if (kt + 2 < Ktiles) load_stage(kt + 2, (kt + 2) % STAGES);
        asm volatile("cp.async.commit_group;\n");

        char* cA = sA + st * ASTAGE;
        char* cB = sB + st * BSTAGE;
        #pragma unroll
        for (int kk = 0; kk < 2; ++kk){
            uint32_t af[MF][4];
            #pragma unroll
            for (int mf = 0; mf < MF; ++mf){
                int r = wm * WMT + mf * 16 + (lane & 15);
                uint32_t addr = smem_u32(cA + r * APITCH + kk * 32 + (lane >> 4) * 16);
                asm volatile("ldmatrix.sync.aligned.m8n8.x4.shared.b16 {%0,%1,%2,%3},[%4];\n"
                    : "=r"(af[mf][0]), "=r"(af[mf][1]), "=r"(af[mf][2]), "=r"(af[mf][3]) : "r"(addr));
            }
            uint32_t bfr[NF][2];
            #pragma unroll
            for (int n2 = 0; n2 < NF/2; ++n2){
                int k = kk * 16 + (lane & 15);
                int gn = (wn * WNT + n2 * 16) / 8 + (lane >> 4);
                uint32_t addr = smem_u32(cB + k * BPITCH + ((gn ^ (k & 7)) * 16));
                uint32_t r0, r1, r2, r3;
                asm volatile("ldmatrix.sync.aligned.m8n8.x4.trans.shared.b16 {%0,%1,%2,%3},[%4];\n"
                    : "=r"(r0), "=r"(r1), "=r"(r2), "=r"(r3) : "r"(addr));
                bfr[n2*2][0]=r0; bfr[n2*2][1]=r1; bfr[n2*2+1][0]=r2; bfr[n2*2+1][1]=r3;
            }
            #pragma unroll
            for (int mf = 0; mf < MF; ++mf)
                #pragma unroll
                for (int nf = 0; nf < NF; ++nf)
                    asm volatile("mma.sync.aligned.m16n8k16.row.col.f32.bf16.bf16.f32 "
                        "{%0,%1,%2,%3},{%4,%5,%6,%7},{%8,%9},{%0,%1,%2,%3};\n"
                        : "+f"(acc[mf][nf][0]), "+f"(acc[mf][nf][1]),
                          "+f"(acc[mf][nf][2]), "+f"(acc[mf][nf][3])
                        : "r"(af[mf][0]), "r"(af[mf][1]), "r"(af[mf][2]), "r"(af[mf][3]),
                          "r"(bfr[nf][0]), "r"(bfr[nf][1]));
        }
    }

    long cz = z * cB;
    #pragma unroll
    for (int mf = 0; mf < MF; ++mf)
        #pragma unroll
        for (int nf = 0; nf < NF; ++nf){
            int gm = bm + wm * WMT + mf * 16 + (lane >> 2);
            int cc = bn + wn * WNT + nf * 8 + (lane & 3) * 2;
            float b0 = biasp ? biasp[cc] : 0.f;
            float b1 = biasp ? biasp[cc + 1] : 0.f;
            if (colsum){ b0 += 0.5f * colsum[cc]; b1 += 0.5f * colsum[cc + 1]; }
            float v00 = acc[mf][nf][0] + b0, v01 = acc[mf][nf][1] + b1;
            float v10 = acc[mf][nf][2] + b0, v11 = acc[mf][nf][3] + b1;
            if (EPI == 0 || EPI == 3){
                float* Cp = (float*)C + cz;
                *(float2*)(Cp + (long)gm * Ndim + cc)       = make_float2(v00, v01);
                *(float2*)(Cp + (long)(gm + 8) * Ndim + cc) = make_float2(v10, v11);
                if (EPI == 3){
                    __nv_bfloat162 t0 = __floats2bfloat162_rn(v00, v01);
                    __nv_bfloat162 t1 = __floats2bfloat162_rn(v10, v11);
                    *(__nv_bfloat162*)(C2 + (long)gm * Ndim + cc)       = t0;
                    *(__nv_bfloat162*)(C2 + (long)(gm + 8) * Ndim + cc) = t1;
                }
            } else {
                v00 = fmaxf(v00, 0.f); v01 = fmaxf(v01, 0.f);
                v10 = fmaxf(v10, 0.f); v11 = fmaxf(v11, 0.f);
                __nv_bfloat16* Cp = (__nv_bfloat16*)C + cz;
                __nv_bfloat162 t0; t0.x = __float2bfloat16(v00); t0.y = __float2bfloat16(v01);
                __nv_bfloat162 t1; t1.x = __float2bfloat16(v10); t1.y = __float2bfloat16(v11);
                *(__nv_bfloat162*)(Cp + (long)gm * Ndim + cc)       = t0;
                *(__nv_bfloat162*)(Cp + (long)(gm + 8) * Ndim + cc) = t1;
            }
        }
}

// ------------------------------ host -----------------------------------------
template<int BN, int EPI>
static void launch_gemm(const __nv_bfloat16* A, const __nv_bfloat16* B, void* C,
                        const float* bias, const float* cs, int K, int N, int batch,
                        long aB, long bB, long cBt, long biasB,
                        __nv_bfloat16* C2 = nullptr){
    constexpr int SMB = STAGES * (BM * 80) + STAGES * (BK * BN * 2);
    cudaFuncSetAttribute(gemm_bf16<BN, EPI>, cudaFuncAttributeMaxDynamicSharedMemorySize, SMB);
    dim3 grid(N / BN, NTOK / BM, batch);
    gemm_bf16<BN, EPI><<<grid, 256, SMB>>>(A, B, C, bias, cs, K, N, aB, bB, cBt, biasB, C2);
}

template<int EPI>
static void launch_k64(const __nv_bfloat16* A, const __nv_bfloat16* B, void* C,
                       const float* bias, const float* cs, int K, int N){
    constexpr int SMB = KST * (KBM * 128) + KST * (KBK * 256);
    cudaFuncSetAttribute(gemm_bk64<EPI>, cudaFuncAttributeMaxDynamicSharedMemorySize, SMB);
    dim3 grid(N / KBN, NTOK / KBM, 1);
    gemm_bk64<EPI><<<grid, 256, SMB>>>(A, B, C, bias, cs, K, N);
}

template<typename T> static T* sym(T* s){ void* p = nullptr; cudaGetSymbolAddress(&p, (const void*)s); return (T*)p; }

extern "C" void kernel_launch(void* const* d_in, const int* in_sizes, int n_in,
                              void* d_out, int out_size){
    (void)in_sizes; (void)n_in; (void)out_size;
    const void*  ids   = d_in[0];
    const float* emb   = (const float*)d_in[1];
    const float* enc_W = (const float*)d_in[2];  const float* enc_b = (const float*)d_in[3];
    const float* s2c_W = (const float*)d_in[4];  const float* s2c_b = (const float*)d_in[5];
    const float* rW1   = (const float*)d_in[6];  const float* rb1   = (const float*)d_in[7];
    const float* rW2   = (const float*)d_in[8];  const float* rb2   = (const float*)d_in[9];
    const float* eW1   = (const float*)d_in[10]; const float* eb1   = (const float*)d_in[11];
    const float* eW2   = (const float*)d_in[12]; const float* eb2   = (const float*)d_in[13];
    const float* c2s_W = (const float*)d_in[14]; const float* c2s_b = (const float*)d_in[15];
    const float* dec_W = (const float*)d_in[16]; const float* dec_b = (const float*)d_in[17];
    const float* out_W = (const float*)d_in[18]; const float* out_b = (const float*)d_in[19];
    float* logits = (float*)d_out;
    float* probs  = logits + (size_t)NTOK * VOCAB;

    __nv_bfloat16 *xbf = sym(g_xbf), *spk = sym(g_spk), *moe = sym(g_moe), *decd = sym(g_decd);
    __nv_bfloat16 *contbf = sym(g_contbf), *eobf = sym(g_eobf), *h1 = sym(g_h1);
    float *cont = sym(g_cont), *eo = sym(g_eo), *wfull = sym(g_wfull);
    __nv_bfloat16 *Wenc = sym(g_Wenc), *Ws2c = sym(g_Ws2c), *We1 = sym(g_We1), *We2 = sym(g_We2);
    __nv_bfloat16 *Wc2s = sym(g_Wc2s), *Wdec = sym(g_Wdec), *Wout = sym(g_Wout);
    float *cs_s2c = sym(g_cs_s2c), *cs_dec = sym(g_cs_dec), *cs_out = sym(g_cs_out);

    detect_kernel<<<1, 256>>>((const unsigned int*)ids);
    gather_kernel<<<NTOK, 256>>>(ids, (const float4*)emb, (__nv_bfloat162*)xbf);

    f2b4_kernel<<<(DMODEL*HDIM/4 + 255)/256, 256>>>((const float4*)enc_W, (__nv_bfloat162*)Wenc, DMODEL*HDIM/4);
    f2b4_kernel<<<(NEXP*MDIM*HEXP/4 + 255)/256, 256>>>((const float4*)eW1, (__nv_bfloat162*)We1, NEXP*MDIM*HEXP/4);
    f2b4_kernel<<<(NEXP*HEXP*MDIM/4 + 255)/256, 256>>>((const float4*)eW2, (__nv_bfloat162*)We2, NEXP*HEXP*MDIM/4);
    f2b4_kernel<<<(MDIM*HDIM/4 + 255)/256, 256>>>((const float4*)c2s_W, (__nv_bfloat162*)Wc2s, MDIM*HDIM/4);
    cudaMemsetAsync(cs_s2c, 0, MDIM * sizeof(float));
    cudaMemsetAsync(cs_dec, 0, DMODEL * sizeof(float));
    cudaMemsetAsync(cs_out, 0, VOCAB * sizeof(float));
    wconv_cs4_kernel<<<dim3(1, 8), 256>>>(s2c_W, Ws2c, cs_s2c, HDIM, MDIM);
    wconv_cs4_kernel<<<dim3(1, 8), 256>>>(dec_W, Wdec, cs_dec, HDIM, DMODEL);
    wconv_cs4_kernel<<<dim3(32, 8), 256>>>(out_W, Wout, cs_out, DMODEL, VOCAB);

    // enc: sigmoid-0.5 -> spk (bf16)
    launch_k64<1>(xbf, Wenc, spk, enc_b, nullptr, DMODEL, HDIM);
    // s2c: fp32 cont + bf16 contbf in one pass, +0.5*colsum correction
    launch_gemm<64, 3>(spk, Ws2c, cont, s2c_b, cs_s2c, HDIM, MDIM, 1, 0, 0, 0, 0, contbf);
    router_kernel<<<NTOK/8, 256>>>(cont, rW1, rb1, rW2, rb2, probs, wfull);
    // experts: dense over all 8 (batched), relu epilogue
    launch_gemm<128, 2>(contbf, We1, h1, eb1, nullptr, MDIM, HEXP, NEXP,
                        0, (long)MDIM*HEXP, (long)NTOK*HEXP, HEXP);
    launch_gemm<64, 0>(h1, We2, eo, eb2, nullptr, HEXP, MDIM, NEXP,
                       (long)NTOK*HEXP, (long)HEXP*MDIM, (long)NTOK*MDIM, MDIM);
    combine_kernel<<<NTOK*MDIM/256, 256>>>(eo, wfull, eobf);
    // c2s: sigmoid-0.5 (K=64 -> single main-loop iteration)
    launch_k64<1>(eobf, Wc2s, moe, c2s_b, nullptr, MDIM, HDIM);
    // dec: centered input, sigmoid-0.5
    launch_k64<1>(moe, Wdec, decd, dec_b, cs_dec, HDIM, DMODEL);
    // out: centered input, fp32 logits
    launch_k64<0>(decd, Wout, logits, out_b, cs_out, DMODEL, VOCAB);
}

// round 14
// speedup vs baseline: 1.0839x; 1.0839x over previous
#include <cuda_runtime.h>
#include <cuda_bf16.h>
#include <stdint.h>

#define NTOK 4096
#define DMODEL 1024
#define HDIM 1024
#define MDIM 64
#define NEXP 8
#define HEXP 512
#define VOCAB 32000

// ---------------- device scratch (module-scope: allocation-free) -------------
__device__ __nv_bfloat16 g_xbf [NTOK*DMODEL];
__device__ __nv_bfloat16 g_spk [NTOK*HDIM];
__device__ __nv_bfloat16 g_moe [NTOK*HDIM];
__device__ __nv_bfloat16 g_decd[NTOK*DMODEL];
__device__ __nv_bfloat16 g_contbf[NTOK*MDIM];
__device__ __nv_bfloat16 g_eobf [NTOK*MDIM];
__device__ __nv_bfloat16 g_h1  [(size_t)NEXP*NTOK*HEXP];
__device__ float g_cont [NTOK*MDIM];
__device__ float g_eo   [(size_t)NEXP*NTOK*MDIM];
__device__ float g_wfull[NTOK*NEXP];
__device__ __nv_bfloat16 g_Wenc[DMODEL*HDIM];
__device__ __nv_bfloat16 g_Ws2c[HDIM*MDIM];
__device__ __nv_bfloat16 g_We1 [NEXP*MDIM*HEXP];
__device__ __nv_bfloat16 g_We2 [NEXP*HEXP*MDIM];
__device__ __nv_bfloat16 g_Wc2s[MDIM*HDIM];
__device__ __nv_bfloat16 g_Wdec[HDIM*DMODEL];
__device__ __nv_bfloat16 g_Wout[(size_t)DMODEL*VOCAB];
__device__ float g_cs_s2c[MDIM];
__device__ float g_cs_dec[DMODEL];
__device__ float g_cs_out[VOCAB];
__device__ int   g_is32;

__device__ __forceinline__ uint32_t smem_u32(const void* p){
    return (uint32_t)__cvta_generic_to_shared(p);
}

// ------------------------------ small kernels --------------------------------
__global__ void detect_kernel(const unsigned int* w){
    __shared__ int any;
    if (threadIdx.x == 0) any = 0;
    __syncthreads();
    int loc = 0;
    for (int i = 2*threadIdx.x + 1; i < 4096; i += 2*blockDim.x)
        if (w[i] != 0u) loc = 1;
    if (loc) atomicOr(&any, 1);
    __syncthreads();
    if (threadIdx.x == 0) g_is32 = any;
}

__global__ void gather_kernel(const void* idsRaw, const float4* __restrict__ emb4,
                              __nv_bfloat162* __restrict__ x2){
    int n = blockIdx.x;
    long long v = g_is32 ? (long long)((const int*)idsRaw)[n]
                         : ((const long long*)idsRaw)[n];
    const float4* src = emb4 + v * (DMODEL/4);
    __nv_bfloat162* dst = x2 + (long)n * (DMODEL/2);
    for (int d = threadIdx.x; d < DMODEL/4; d += blockDim.x){
        float4 t = src[d];
        dst[2*d]   = __floats2bfloat162_rn(t.x, t.y);
        dst[2*d+1] = __floats2bfloat162_rn(t.z, t.w);
    }
}

// vectorized fp32->bf16 (n must be divisible by 4)
__global__ void f2b4_kernel(const float4* __restrict__ s, __nv_bfloat162* __restrict__ d, int n4){
    int i = blockIdx.x * 256 + threadIdx.x;
    if (i < n4){
        float4 v = s[i];
        d[2*i]   = __floats2bfloat162_rn(v.x, v.y);
        d[2*i+1] = __floats2bfloat162_rn(v.z, v.w);
    }
}

// vectorized convert + column sums (cs pre-zeroed). Each thread: 4 consecutive
// columns. grid (ceil(N/4/256), SEGS). Ndim divisible by 4.
__global__ void wconv_cs4_kernel(const float* __restrict__ W, __nv_bfloat16* __restrict__ Wb,
                                 float* __restrict__ cs, int Kdim, int Ndim){
    int j4 = blockIdx.x * 256 + threadIdx.x;
    if (j4 * 4 >= Ndim) return;
    int j = j4 * 4;
    int seg = Kdim / gridDim.y;
    int k0 = blockIdx.y * seg;
    float s0 = 0.f, s1 = 0.f, s2 = 0.f, s3 = 0.f;
    for (int k = k0; k < k0 + seg; ++k){
        float4 v = *(const float4*)(W + (long)k * Ndim + j);
        s0 += v.x; s1 += v.y; s2 += v.z; s3 += v.w;
        __nv_bfloat162* o = (__nv_bfloat162*)(Wb + (long)k * Ndim + j);
        o[0] = __floats2bfloat162_rn(v.x, v.y);
        o[1] = __floats2bfloat162_rn(v.z, v.w);
    }
    atomicAdd(&cs[j],     s0);
    atomicAdd(&cs[j + 1], s1);
    atomicAdd(&cs[j + 2], s2);
    atomicAdd(&cs[j + 3], s3);
}

__global__ void router_kernel(const float* __restrict__ cont,
                              const float* __restrict__ rW1, const float* __restrict__ rb1,
                              const float* __restrict__ rW2, const float* __restrict__ rb2,
                              float* __restrict__ probs, float* __restrict__ wfull){
    int n = blockIdx.x * 8 + (threadIdx.x >> 5);
    int lane = threadIdx.x & 31;
    const float* cn = cont + (long)n * MDIM;
    float h0 = rb1[lane], h1 = rb1[lane + 32];
    #pragma unroll 8
    for (int k = 0; k < 64; ++k){
        float c = cn[k];
        h0 += c * rW1[k * 64 + lane];
        h1 += c * rW1[k * 64 + lane + 32];
    }
    h0 = tanhf(h0); h1 = tanhf(h1);
    float lg[8];
    #pragma unroll
    for (int e = 0; e < 8; ++e){
        float v = h0 * rW2[lane * 8 + e] + h1 * rW2[(lane + 32) * 8 + e];
        #pragma unroll
        for (int o = 16; o > 0; o >>= 1) v += __shfl_xor_sync(0xffffffffu, v, o);
        lg[e] = v + rb2[e];
    }
    float mx = lg[0];
    #pragma unroll
    for (int e = 1; e < 8; ++e) mx = fmaxf(mx, lg[e]);
    float se = 0.f;
    #pragma unroll
    for (int e = 0; e < 8; ++e){ lg[e] = expf(lg[e] - mx); se += lg[e]; }
    float inv = 1.f / se;
    #pragma unroll
    for (int e = 0; e < 8; ++e) lg[e] *= inv;
    int i1 = 0; float v1 = lg[0];
    #pragma unroll
    for (int e = 1; e < 8; ++e) if (lg[e] > v1){ v1 = lg[e]; i1 = e; }
    int i2 = -1; float v2 = -1.f;
    #pragma unroll
    for (int e = 0; e < 8; ++e) if (e != i1 && lg[e] > v2){ v2 = lg[e]; i2 = e; }
    float winv = 1.f / (v1 + v2);
    if (lane == 0){
        #pragma unroll
        for (int e = 0; e < 8; ++e){
            probs[(long)n * 8 + e] = lg[e];
            wfull[(long)n * 8 + e] = (e == i1) ? v1 * winv : (e == i2) ? v2 * winv : 0.f;
        }
    }
}

__global__ void combine_kernel(const float* __restrict__ eo, const float* __restrict__ wfull,
                               __nv_bfloat16* __restrict__ out){
    int idx = blockIdx.x * 256 + threadIdx.x;
    int n = idx >> 6, m = idx & 63;
    float s = 0.f;
    #pragma unroll
    for (int e = 0; e < 8; ++e)
        s += wfull[(long)n * 8 + e] * eo[((long)e * NTOK + n) * MDIM + m];
    out[idx] = __float2bfloat16(s);
}

// ---------------- BIG GEMM: BM=128 BN=128 BK=64, 256 threads -----------------
// C[4096 x N] = A[4096 x K] * B[K x N] (+bias +0.5*colsum); warp tile 64x32.
// EPI 0: f32 out ; 1: bf16 out = sigmoid(v)-0.5 = 0.5*tanh(v/2).
#define KBM 128
#define KBN 128
#define KBK 64
#define KST 3

template<int EPI>
__global__ void __launch_bounds__(256) gemm_bk64(
    const __nv_bfloat16* __restrict__ A, const __nv_bfloat16* __restrict__ B,
    void* __restrict__ C, const float* __restrict__ bias, const float* __restrict__ colsum,
    int Kdim, int Ndim)
{
    constexpr int ASTG = KBM * 128;
    constexpr int BSTG = KBK * 256;
    extern __shared__ char smem[];
    char* sA = smem;
    char* sB = smem + KST * ASTG;

    int tid = threadIdx.x, lane = tid & 31, wid = tid >> 5;
    int wm = wid >> 2, wn = wid & 3;
    int bm = blockIdx.y * KBM, bn = blockIdx.x * KBN;
    const int Kt = Kdim / KBK;

    auto load_stage = [&](int kt, int st){
        const __nv_bfloat16* Ag = A + (long)bm * Kdim + kt * KBK;
        #pragma unroll
        for (int i = 0; i < 4; ++i){
            int idx = tid + i * 256;
            int row = idx >> 3, g = idx & 7;
            uint32_t dst = smem_u32(sA + st * ASTG + row * 128 + ((g ^ (row & 7)) * 16));
            const void* src = Ag + (long)row * Kdim + g * 8;
            asm volatile("cp.async.cg.shared.global [%0],[%1],16;\n" :: "r"(dst), "l"(src));
        }
        const __nv_bfloat16* Bg = B + (long)(kt * KBK) * Ndim + bn;
        #pragma unroll
        for (int i = 0; i < 4; ++i){
            int idx = tid + i * 256;
            int k = idx >> 4, g = idx & 15;
            uint32_t dst = smem_u32(sB + st * BSTG + k * 256 + ((g ^ (k & 15)) * 16));
            const void* src = Bg + (long)k * Ndim + g * 8;
            asm volatile("cp.async.cg.shared.global [%0],[%1],16;\n" :: "r"(dst), "l"(src));
        }
    };

    float acc[4][4][4];
    #pragma unroll
    for (int i = 0; i < 4; ++i)
        #pragma unroll
        for (int j = 0; j < 4; ++j){ acc[i][j][0]=0.f; acc[i][j][1]=0.f; acc[i][j][2]=0.f; acc[i][j][3]=0.f; }

    load_stage(0, 0);
    asm volatile("cp.async.commit_group;\n");
    if (Kt > 1) load_stage(1, 1);
    asm volatile("cp.async.commit_group;\n");

    for (int kt = 0; kt < Kt; ++kt){
        asm volatile("cp.async.wait_group 1;\n");
        __syncthreads();
        int st = kt % KST;
        if (kt + 2 < Kt) load_stage(kt + 2, (kt + 2) % KST);
        asm volatile("cp.async.commit_group;\n");

        char* cA = sA + st * ASTG;
        char* cB = sB + st * BSTG;
        #pragma unroll
        for (int kk = 0; kk < 4; ++kk){
            uint32_t af[4][4];
            #pragma unroll
            for (int mf = 0; mf < 4; ++mf){
                int r = wm * 64 + mf * 16 + (lane & 15);
                int g = kk * 2 + (lane >> 4);
                uint32_t addr = smem_u32(cA + r * 128 + ((g ^ (r & 7)) * 16));
                asm volatile("ldmatrix.sync.aligned.m8n8.x4.shared.b16 {%0,%1,%2,%3},[%4];\n"
                    : "=r"(af[mf][0]), "=r"(af[mf][1]), "=r"(af[mf][2]), "=r"(af[mf][3]) : "r"(addr));
            }
            uint32_t bfr[4][2];
            #pragma unroll
            for (int n2 = 0; n2 < 2; ++n2){
                int k = kk * 16 + (lane & 15);
                int gn = wn * 4 + n2 * 2 + (lane >> 4);
                uint32_t addr = smem_u32(cB + k * 256 + ((gn ^ (k & 15)) * 16));
                uint32_t r0, r1, r2, r3;
                asm volatile("ldmatrix.sync.aligned.m8n8.x4.trans.shared.b16 {%0,%1,%2,%3},[%4];\n"
                    : "=r"(r0), "=r"(r1), "=r"(r2), "=r"(r3) : "r"(addr));
                bfr[n2*2][0]=r0; bfr[n2*2][1]=r1; bfr[n2*2+1][0]=r2; bfr[n2*2+1][1]=r3;
            }
            #pragma unroll
            for (int mf = 0; mf < 4; ++mf)
                #pragma unroll
                for (int nf = 0; nf < 4; ++nf)
                    asm volatile("mma.sync.aligned.m16n8k16.row.col.f32.bf16.bf16.f32 "
                        "{%0,%1,%2,%3},{%4,%5,%6,%7},{%8,%9},{%0,%1,%2,%3};\n"
                        : "+f"(acc[mf][nf][0]), "+f"(acc[mf][nf][1]),
                          "+f"(acc[mf][nf][2]), "+f"(acc[mf][nf][3])
                        : "r"(af[mf][0]), "r"(af[mf][1]), "r"(af[mf][2]), "r"(af[mf][3]),
                          "r"(bfr[nf][0]), "r"(bfr[nf][1]));
        }
    }

    #pragma unroll
    for (int mf = 0; mf < 4; ++mf)
        #pragma unroll
        for (int nf = 0; nf < 4; ++nf){
            int gm = bm + wm * 64 + mf * 16 + (lane >> 2);
            int cc = bn + wn * 32 + nf * 8 + (lane & 3) * 2;
            float b0 = bias ? bias[cc] : 0.f;
            float b1 = bias ? bias[cc + 1] : 0.f;
            if (colsum){ b0 += 0.5f * colsum[cc]; b1 += 0.5f * colsum[cc + 1]; }
            float v00 = acc[mf][nf][0] + b0, v01 = acc[mf][nf][1] + b1;
            float v10 = acc[mf][nf][2] + b0, v11 = acc[mf][nf][3] + b1;
            if (EPI == 0){
                float* Cp = (float*)C;
                *(float2*)(Cp + (long)gm * Ndim + cc)       = make_float2(v00, v01);
                *(float2*)(Cp + (long)(gm + 8) * Ndim + cc) = make_float2(v10, v11);
            } else {
                v00 = 0.5f * tanhf(0.5f * v00); v01 = 0.5f * tanhf(0.5f * v01);
                v10 = 0.5f * tanhf(0.5f * v10); v11 = 0.5f * tanhf(0.5f * v11);
                __nv_bfloat16* Cp = (__nv_bfloat16*)C;
                __nv_bfloat162 t0; t0.x = __float2bfloat16(v00); t0.y = __float2bfloat16(v01);
                __nv_bfloat162 t1; t1.x = __float2bfloat16(v10); t1.y = __float2bfloat16(v11);
                *(__nv_bfloat162*)(Cp + (long)gm * Ndim + cc)       = t0;
                *(__nv_bfloat162*)(Cp + (long)(gm + 8) * Ndim + cc) = t1;
            }
        }
}

// --------------------- small GEMM (proven path) ------------------------------
// EPI 0: f32 ; 2: relu bf16 ; 3: f32 to C AND plain bf16 to C2.
#define BM 128
#define BK 32
#define STAGES 3

template<int BN, int EPI>
__global__ void __launch_bounds__(256) gemm_bf16(
    const __nv_bfloat16* __restrict__ A, const __nv_bfloat16* __restrict__ B,
    void* __restrict__ C, const float* __restrict__ bias, const float* __restrict__ colsum,
    int Kdim, int Ndim, long aB, long bB, long cB, long biasB,
    __nv_bfloat16* __restrict__ C2)
{
    constexpr int WARPS_N = (BN == 128) ? 4 : 2;
    constexpr int WARPS_M = 8 / WARPS_N;
    constexpr int WMT = BM / WARPS_M;
    constexpr int WNT = BN / WARPS_N;
    constexpr int MF = WMT / 16;
    constexpr int NF = WNT / 8;
    constexpr int APITCH = 80;
    constexpr int ASTAGE = BM * APITCH;
    constexpr int BPITCH = BN * 2;
    constexpr int BSTAGE = BK * BPITCH;
    constexpr int GR = BN / 8;
    constexpr int BROWS = 256 / GR;
    constexpr int BPASSES = BK / BROWS;

    extern __shared__ char smem[];
    char* sA = smem;
    char* sB = smem + STAGES * ASTAGE;

    int z = blockIdx.z;
    A += z * aB; B += z * bB;
    const float* biasp = bias ? bias + z * biasB : nullptr;

    int tid = threadIdx.x, lane = tid & 31, wid = tid >> 5;
    int wm = wid / WARPS_N, wn = wid % WARPS_N;
    int bm = blockIdx.y * BM, bn = blockIdx.x * BN;
    int am = tid >> 2, ag = tid & 3;
    int bkr = tid / GR, bg = tid % GR;
    const int Ktiles = Kdim / BK;

    auto load_stage = [&](int kt, int st){
        const __nv_bfloat16* Ag = A + (long)bm * Kdim + kt * BK;
        #pragma unroll
        for (int p = 0; p < 2; ++p){
            int row = am + p * 64;
            uint32_t dst = smem_u32(sA + st * ASTAGE + row * APITCH + ag * 16);
            const void* src = Ag + (long)row * Kdim + ag * 8;
            asm volatile("cp.async.cg.shared.global [%0],[%1],16;\n" :: "r"(dst), "l"(src));
        }
        const __nv_bfloat16* Bg = B + (long)(kt * BK) * Ndim + bn;
        #pragma unroll
        for (int p = 0; p < BPASSES; ++p){
            int k = bkr + p * BROWS;
            uint32_t dst = smem_u32(sB + st * BSTAGE + k * BPITCH + ((bg ^ (k & 7)) * 16));
            const void* src = Bg + (long)k * Ndim + bg * 8;
            asm volatile("cp.async.cg.shared.global [%0],[%1],16;\n" :: "r"(dst), "l"(src));
        }
    };

    float acc[MF][NF][4];
    #pragma unroll
    for (int i = 0; i < MF; ++i)
        #pragma unroll
        for (int j = 0; j < NF; ++j){ acc[i][j][0]=0.f; acc[i][j][1]=0.f; acc[i][j][2]=0.f; acc[i][j][3]=0.f; }

    load_stage(0, 0);
    asm volatile("cp.async.commit_group;\n");
    if (Ktiles > 1) load_stage(1, 1);
    asm volatile("cp.async.commit_group;\n");

    for (int kt = 0; kt < Ktiles; ++kt){
        asm volatile("cp.async.wait_group 1;\n");
        __syncthreads();
        int st = kt % STAGES;
        if (kt + 2 < Ktiles) load_stage(kt + 2, (kt + 2) % STAGES);
        asm volatile("cp.async.commit_group;\n");

        char* cA = sA + st * ASTAGE;
        char* cB = sB + st * BSTAGE;
        #pragma unroll
        for (int kk = 0; kk < 2; ++kk){
            uint32_t af[MF][4];
            #pragma unroll
            for (int mf = 0; mf < MF; ++mf){
                int r = wm * WMT + mf * 16 + (lane & 15);
                uint32_t addr = smem_u32(cA + r * APITCH + kk * 32 + (lane >> 4) * 16);
                asm volatile("ldmatrix.sync.aligned.m8n8.x4.shared.b16 {%0,%1,%2,%3},[%4];\n"
                    : "=r"(af[mf][0]), "=r"(af[mf][1]), "=r"(af[mf][2]), "=r"(af[mf][3]) : "r"(addr));
            }
            uint32_t bfr[NF][2];
            #pragma unroll
            for (int n2 = 0; n2 < NF/2; ++n2){
                int k = kk * 16 + (lane & 15);
                int gn = (wn * WNT + n2 * 16) / 8 + (lane >> 4);
                uint32_t addr = smem_u32(cB + k * BPITCH + ((gn ^ (k & 7)) * 16));
                uint32_t r0, r1, r2, r3;
                asm volatile("ldmatrix.sync.aligned.m8n8.x4.trans.shared.b16 {%0,%1,%2,%3},[%4];\n"
                    : "=r"(r0), "=r"(r1), "=r"(r2), "=r"(r3) : "r"(addr));
                bfr[n2*2][0]=r0; bfr[n2*2][1]=r1; bfr[n2*2+1][0]=r2; bfr[n2*2+1][1]=r3;
            }
            #pragma unroll
            for (int mf = 0; mf < MF; ++mf)
                #pragma unroll
                for (int nf = 0; nf < NF; ++nf)
                    asm volatile("mma.sync.aligned.m16n8k16.row.col.f32.bf16.bf16.f32 "
                        "{%0,%1,%2,%3},{%4,%5,%6,%7},{%8,%9},{%0,%1,%2,%3};\n"
                        : "+f"(acc[mf][nf][0]), "+f"(acc[mf][nf][1]),
                          "+f"(acc[mf][nf][2]), "+f"(acc[mf][nf][3])
                        : "r"(af[mf][0]), "r"(af[mf][1]), "r"(af[mf][2]), "r"(af[mf][3]),
                          "r"(bfr[nf][0]), "r"(bfr[nf][1]));
        }
    }

    long cz = z * cB;
    #pragma unroll
    for (int mf = 0; mf < MF; ++mf)
        #pragma unroll
        for (int nf = 0; nf < NF; ++nf){
            int gm = bm + wm * WMT + mf * 16 + (lane >> 2);
            int cc = bn + wn * WNT + nf * 8 + (lane & 3) * 2;
            float b0 = biasp ? biasp[cc] : 0.f;
            float b1 = biasp ? biasp[cc + 1] : 0.f;
            if (colsum){ b0 += 0.5f * colsum[cc]; b1 += 0.5f * colsum[cc + 1]; }
            float v00 = acc[mf][nf][0] + b0, v01 = acc[mf][nf][1] + b1;
            float v10 = acc[mf][nf][2] + b0, v11 = acc[mf][nf][3] + b1;
            if (EPI == 0 || EPI == 3){
                float* Cp = (float*)C + cz;
                *(float2*)(Cp + (long)gm * Ndim + cc)       = make_float2(v00, v01);
                *(float2*)(Cp + (long)(gm + 8) * Ndim + cc) = make_float2(v10, v11);
                if (EPI == 3){
                    __nv_bfloat162 t0 = __floats2bfloat162_rn(v00, v01);
                    __nv_bfloat162 t1 = __floats2bfloat162_rn(v10, v11);
                    *(__nv_bfloat162*)(C2 + (long)gm * Ndim + cc)       = t0;
                    *(__nv_bfloat162*)(C2 + (long)(gm + 8) * Ndim + cc) = t1;
                }
            } else {
                v00 = fmaxf(v00, 0.f); v01 = fmaxf(v01, 0.f);
                v10 = fmaxf(v10, 0.f); v11 = fmaxf(v11, 0.f);
                __nv_bfloat16* Cp = (__nv_bfloat16*)C + cz;
                __nv_bfloat162 t0; t0.x = __float2bfloat16(v00); t0.y = __float2bfloat16(v01);
                __nv_bfloat162 t1; t1.x = __float2bfloat16(v10); t1.y = __float2bfloat16(v11);
                *(__nv_bfloat162*)(Cp + (long)gm * Ndim + cc)       = t0;
                *(__nv_bfloat162*)(Cp + (long)(gm + 8) * Ndim + cc) = t1;
            }
        }
}

// ------------------------------ host -----------------------------------------
template<int BN, int EPI>
static void launch_gemm(const __nv_bfloat16* A, const __nv_bfloat16* B, void* C,
                        const float* bias, const float* cs, int K, int N, int batch,
                        long aB, long bB, long cBt, long biasB,
                        __nv_bfloat16* C2 = nullptr){
    constexpr int SMB = STAGES * (BM * 80) + STAGES * (BK * BN * 2);
    cudaFuncSetAttribute(gemm_bf16<BN, EPI>, cudaFuncAttributeMaxDynamicSharedMemorySize, SMB);
    dim3 grid(N / BN, NTOK / BM, batch);
    gemm_bf16<BN, EPI><<<grid, 256, SMB>>>(A, B, C, bias, cs, K, N, aB, bB, cBt, biasB, C2);
}

template<int EPI>
static void launch_k64(const __nv_bfloat16* A, const __nv_bfloat16* B, void* C,
                       const float* bias, const float* cs, int K, int N){
    constexpr int SMB = KST * (KBM * 128) + KST * (KBK * 256);
    cudaFuncSetAttribute(gemm_bk64<EPI>, cudaFuncAttributeMaxDynamicSharedMemorySize, SMB);
    dim3 grid(N / KBN, NTOK / KBM, 1);
    gemm_bk64<EPI><<<grid, 256, SMB>>>(A, B, C, bias, cs, K, N);
}

template<typename T> static T* sym(T* s){ void* p = nullptr; cudaGetSymbolAddress(&p, (const void*)s); return (T*)p; }

extern "C" void kernel_launch(void* const* d_in, const int* in_sizes, int n_in,
                              void* d_out, int out_size){
    (void)in_sizes; (void)n_in; (void)out_size;
    const void*  ids   = d_in[0];
    const float* emb   = (const float*)d_in[1];
    const float* enc_W = (const float*)d_in[2];  const float* enc_b = (const float*)d_in[3];
    const float* s2c_W = (const float*)d_in[4];  const float* s2c_b = (const float*)d_in[5];
    const float* rW1   = (const float*)d_in[6];  const float* rb1   = (const float*)d_in[7];
    const float* rW2   = (const float*)d_in[8];  const float* rb2   = (const float*)d_in[9];
    const float* eW1   = (const float*)d_in[10]; const float* eb1   = (const float*)d_in[11];
    const float* eW2   = (const float*)d_in[12]; const float* eb2   = (const float*)d_in[13];
    const float* c2s_W = (const float*)d_in[14]; const float* c2s_b = (const float*)d_in[15];
    const float* dec_W = (const float*)d_in[16]; const float* dec_b = (const float*)d_in[17];
    const float* out_W = (const float*)d_in[18]; const float* out_b = (const float*)d_in[19];
    float* logits = (float*)d_out;
    float* probs  = logits + (size_t)NTOK * VOCAB;

    __nv_bfloat16 *xbf = sym(g_xbf), *spk = sym(g_spk), *moe = sym(g_moe), *decd = sym(g_decd);
    __nv_bfloat16 *contbf = sym(g_contbf), *eobf = sym(g_eobf), *h1 = sym(g_h1);
    float *cont = sym(g_cont), *eo = sym(g_eo), *wfull = sym(g_wfull);
    __nv_bfloat16 *Wenc = sym(g_Wenc), *Ws2c = sym(g_Ws2c), *We1 = sym(g_We1), *We2 = sym(g_We2);
    __nv_bfloat16 *Wc2s = sym(g_Wc2s), *Wdec = sym(g_Wdec), *Wout = sym(g_Wout);
    float *cs_s2c = sym(g_cs_s2c), *cs_dec = sym(g_cs_dec), *cs_out = sym(g_cs_out);

    detect_kernel<<<1, 256>>>((const unsigned int*)ids);
    gather_kernel<<<NTOK, 256>>>(ids, (const float4*)emb, (__nv_bfloat162*)xbf);

    f2b4_kernel<<<(DMODEL*HDIM/4 + 255)/256, 256>>>((const float4*)enc_W, (__nv_bfloat162*)Wenc, DMODEL*HDIM/4);
    f2b4_kernel<<<(NEXP*MDIM*HEXP/4 + 255)/256, 256>>>((const float4*)eW1, (__nv_bfloat162*)We1, NEXP*MDIM*HEXP/4);
    f2b4_kernel<<<(NEXP*HEXP*MDIM/4 + 255)/256, 256>>>((const float4*)eW2, (__nv_bfloat162*)We2, NEXP*HEXP*MDIM/4);
    f2b4_kernel<<<(MDIM*HDIM/4 + 255)/256, 256>>>((const float4*)c2s_W, (__nv_bfloat162*)Wc2s, MDIM*HDIM/4);
    cudaMemsetAsync(cs_s2c, 0, MDIM * sizeof(float));
    cudaMemsetAsync(cs_dec, 0, DMODEL * sizeof(float));
    cudaMemsetAsync(cs_out, 0, VOCAB * sizeof(float));
    // high-parallelism grids: many K-segments so the streaming converts are
    // MLP-rich (R10's grids starved DRAM latency hiding on the 128MB out_W).
    wconv_cs4_kernel<<<dim3(1, 64), 256>>>(s2c_W, Ws2c, cs_s2c, HDIM, MDIM);
    wconv_cs4_kernel<<<dim3(1, 64), 256>>>(dec_W, Wdec, cs_dec, HDIM, DMODEL);
    wconv_cs4_kernel<<<dim3(32, 32), 256>>>(out_W, Wout, cs_out, DMODEL, VOCAB);

    // enc: sigmoid-0.5 -> spk (bf16)
    launch_k64<1>(xbf, Wenc, spk, enc_b, nullptr, DMODEL, HDIM);
    // s2c: fp32 cont + bf16 contbf in one pass, +0.5*colsum correction
    launch_gemm<64, 3>(spk, Ws2c, cont, s2c_b, cs_s2c, HDIM, MDIM, 1, 0, 0, 0, 0, contbf);
    router_kernel<<<NTOK/8, 256>>>(cont, rW1, rb1, rW2, rb2, probs, wfull);
    // experts: dense over all 8 (batched), relu epilogue
    launch_gemm<128, 2>(contbf, We1, h1, eb1, nullptr, MDIM, HEXP, NEXP,
                        0, (long)MDIM*HEXP, (long)NTOK*HEXP, HEXP);
    launch_gemm<64, 0>(h1, We2, eo, eb2, nullptr, HEXP, MDIM, NEXP,
                       (long)NTOK*HEXP, (long)HEXP*MDIM, (long)NTOK*MDIM, MDIM);
    combine_kernel<<<NTOK*MDIM/256, 256>>>(eo, wfull, eobf);
    // c2s: sigmoid-0.5 (K=64 -> single main-loop iteration)
    launch_k64<1>(eobf, Wc2s, moe, c2s_b, nullptr, MDIM, HDIM);
    // dec: centered input, sigmoid-0.5
    launch_k64<1>(moe, Wdec, decd, dec_b, cs_dec, HDIM, DMODEL);
    // out: centered input, fp32 logits
    launch_k64<0>(decd, Wout, logits, out_b, cs_out, DMODEL, VOCAB);
}

// round 17
// speedup vs baseline: 1.1043x; 1.0188x over previous
#include <cuda_runtime.h>
#include <cuda_bf16.h>
#include <stdint.h>

#define NTOK 4096
#define DMODEL 1024
#define HDIM 1024
#define MDIM 64
#define NEXP 8
#define HEXP 512
#define VOCAB 32000

// ---------------- device scratch (module-scope: allocation-free) -------------
__device__ __nv_bfloat16 g_xbf [NTOK*DMODEL];
__device__ __nv_bfloat16 g_spk [NTOK*HDIM];
__device__ __nv_bfloat16 g_moe [NTOK*HDIM];
__device__ __nv_bfloat16 g_decd[NTOK*DMODEL];
__device__ __nv_bfloat16 g_contbf[NTOK*MDIM];
__device__ __nv_bfloat16 g_eobf [NTOK*MDIM];
__device__ __nv_bfloat16 g_h1  [(size_t)NEXP*NTOK*HEXP];
__device__ float g_cont [NTOK*MDIM];
__device__ float g_eo   [(size_t)NEXP*NTOK*MDIM];
__device__ float g_wfull[NTOK*NEXP];
__device__ __nv_bfloat16 g_Wenc[DMODEL*HDIM];
__device__ __nv_bfloat16 g_Ws2c[HDIM*MDIM];
__device__ __nv_bfloat16 g_We1 [NEXP*MDIM*HEXP];
__device__ __nv_bfloat16 g_We2 [NEXP*HEXP*MDIM];
__device__ __nv_bfloat16 g_Wc2s[MDIM*HDIM];
__device__ __nv_bfloat16 g_Wdec[HDIM*DMODEL];
__device__ __nv_bfloat16 g_Wout[(size_t)DMODEL*VOCAB];
__device__ float g_cs_s2c[MDIM];
__device__ float g_cs_dec[DMODEL];
__device__ float g_cs_out[VOCAB];
__device__ int   g_is32;

__device__ __forceinline__ uint32_t smem_u32(const void* p){
    return (uint32_t)__cvta_generic_to_shared(p);
}

// ------------------------------ small kernels --------------------------------
__global__ void detect_kernel(const unsigned int* w){
    __shared__ int any;
    if (threadIdx.x == 0) any = 0;
    __syncthreads();
    int loc = 0;
    for (int i = 2*threadIdx.x + 1; i < 4096; i += 2*blockDim.x)
        if (w[i] != 0u) loc = 1;
    if (loc) atomicOr(&any, 1);
    __syncthreads();
    if (threadIdx.x == 0) g_is32 = any;
}

__global__ void gather_kernel(const void* idsRaw, const float4* __restrict__ emb4,
                              __nv_bfloat162* __restrict__ x2){
    int n = blockIdx.x;
    long long v = g_is32 ? (long long)((const int*)idsRaw)[n]
                         : ((const long long*)idsRaw)[n];
    const float4* src = emb4 + v * (DMODEL/4);
    __nv_bfloat162* dst = x2 + (long)n * (DMODEL/2);
    for (int d = threadIdx.x; d < DMODEL/4; d += blockDim.x){
        float4 t = src[d];
        dst[2*d]   = __floats2bfloat162_rn(t.x, t.y);
        dst[2*d+1] = __floats2bfloat162_rn(t.z, t.w);
    }
}

// vectorized fp32->bf16 (n must be divisible by 4)
__global__ void f2b4_kernel(const float4* __restrict__ s, __nv_bfloat162* __restrict__ d, int n4){
    int i = blockIdx.x * 256 + threadIdx.x;
    if (i < n4){
        float4 v = s[i];
        d[2*i]   = __floats2bfloat162_rn(v.x, v.y);
        d[2*i+1] = __floats2bfloat162_rn(v.z, v.w);
    }
}

// vectorized convert + column sums (cs pre-zeroed). Each thread: 4 consecutive
// columns. grid (ceil(N/4/256), SEGS). Ndim divisible by 4.
__global__ void wconv_cs4_kernel(const float* __restrict__ W, __nv_bfloat16* __restrict__ Wb,
                                 float* __restrict__ cs, int Kdim, int Ndim){
    int j4 = blockIdx.x * 256 + threadIdx.x;
    if (j4 * 4 >= Ndim) return;
    int j = j4 * 4;
    int seg = Kdim / gridDim.y;
    int k0 = blockIdx.y * seg;
    float s0 = 0.f, s1 = 0.f, s2 = 0.f, s3 = 0.f;
    for (int k = k0; k < k0 + seg; ++k){
        float4 v = *(const float4*)(W + (long)k * Ndim + j);
        s0 += v.x; s1 += v.y; s2 += v.z; s3 += v.w;
        __nv_bfloat162* o = (__nv_bfloat162*)(Wb + (long)k * Ndim + j);
        o[0] = __floats2bfloat162_rn(v.x, v.y);
        o[1] = __floats2bfloat162_rn(v.z, v.w);
    }
    atomicAdd(&cs[j],     s0);
    atomicAdd(&cs[j + 1], s1);
    atomicAdd(&cs[j + 2], s2);
    atomicAdd(&cs[j + 3], s3);
}

__global__ void router_kernel(const float* __restrict__ cont,
                              const float* __restrict__ rW1, const float* __restrict__ rb1,
                              const float* __restrict__ rW2, const float* __restrict__ rb2,
                              float* __restrict__ probs, float* __restrict__ wfull){
    int n = blockIdx.x * 8 + (threadIdx.x >> 5);
    int lane = threadIdx.x & 31;
    const float* cn = cont + (long)n * MDIM;
    float h0 = rb1[lane], h1 = rb1[lane + 32];
    #pragma unroll 8
    for (int k = 0; k < 64; ++k){
        float c = cn[k];
        h0 += c * rW1[k * 64 + lane];
        h1 += c * rW1[k * 64 + lane + 32];
    }
    h0 = tanhf(h0); h1 = tanhf(h1);
    float lg[8];
    #pragma unroll
    for (int e = 0; e < 8; ++e){
        float v = h0 * rW2[lane * 8 + e] + h1 * rW2[(lane + 32) * 8 + e];
        #pragma unroll
        for (int o = 16; o > 0; o >>= 1) v += __shfl_xor_sync(0xffffffffu, v, o);
        lg[e] = v + rb2[e];
    }
    float mx = lg[0];
    #pragma unroll
    for (int e = 1; e < 8; ++e) mx = fmaxf(mx, lg[e]);
    float se = 0.f;
    #pragma unroll
    for (int e = 0; e < 8; ++e){ lg[e] = expf(lg[e] - mx); se += lg[e]; }
    float inv = 1.f / se;
    #pragma unroll
    for (int e = 0; e < 8; ++e) lg[e] *= inv;
    int i1 = 0; float v1 = lg[0];
    #pragma unroll
    for (int e = 1; e < 8; ++e) if (lg[e] > v1){ v1 = lg[e]; i1 = e; }
    int i2 = -1; float v2 = -1.f;
    #pragma unroll
    for (int e = 0; e < 8; ++e) if (e != i1 && lg[e] > v2){ v2 = lg[e]; i2 = e; }
    float winv = 1.f / (v1 + v2);
    if (lane == 0){
        #pragma unroll
        for (int e = 0; e < 8; ++e){
            probs[(long)n * 8 + e] = lg[e];
            wfull[(long)n * 8 + e] = (e == i1) ? v1 * winv : (e == i2) ? v2 * winv : 0.f;
        }
    }
}

__global__ void combine_kernel(const float* __restrict__ eo, const float* __restrict__ wfull,
                               __nv_bfloat16* __restrict__ out){
    int idx = blockIdx.x * 256 + threadIdx.x;
    int n = idx >> 6, m = idx & 63;
    float s = 0.f;
    #pragma unroll
    for (int e = 0; e < 8; ++e)
        s += wfull[(long)n * 8 + e] * eo[((long)e * NTOK + n) * MDIM + m];
    out[idx] = __float2bfloat16(s);
}

// ---------------- BIG GEMM: BM=128 BN=128 BK=64, 256 threads -----------------
// C[4096 x N] = A[4096 x K] * B[K x N] (+bias +0.5*colsum); warp tile 64x32.
// EPI 0: f32 out ; 1: bf16 out = sigmoid(v)-0.5 = 0.5*tanh(v/2).
#define KBM 128
#define KBN 128
#define KBK 64
#define KST 3

template<int EPI>
__global__ void __launch_bounds__(256) gemm_bk64(
    const __nv_bfloat16* __restrict__ A, const __nv_bfloat16* __restrict__ B,
    void* __restrict__ C, const float* __restrict__ bias, const float* __restrict__ colsum,
    int Kdim, int Ndim)
{
    constexpr int ASTG = KBM * 128;
    constexpr int BSTG = KBK * 256;
    extern __shared__ char smem[];
    char* sA = smem;
    char* sB = smem + KST * ASTG;

    int tid = threadIdx.x, lane = tid & 31, wid = tid >> 5;
    int wm = wid >> 2, wn = wid & 3;
    int bm = blockIdx.y * KBM, bn = blockIdx.x * KBN;
    const int Kt = Kdim / KBK;

    auto load_stage = [&](int kt, int st){
        const __nv_bfloat16* Ag = A + (long)bm * Kdim + kt * KBK;
        #pragma unroll
        for (int i = 0; i < 4; ++i){
            int idx = tid + i * 256;
            int row = idx >> 3, g = idx & 7;
            uint32_t dst = smem_u32(sA + st * ASTG + row * 128 + ((g ^ (row & 7)) * 16));
            const void* src = Ag + (long)row * Kdim + g * 8;
            asm volatile("cp.async.cg.shared.global [%0],[%1],16;\n" :: "r"(dst), "l"(src));
        }
        const __nv_bfloat16* Bg = B + (long)(kt * KBK) * Ndim + bn;
        #pragma unroll
        for (int i = 0; i < 4; ++i){
            int idx = tid + i * 256;
            int k = idx >> 4, g = idx & 15;
            uint32_t dst = smem_u32(sB + st * BSTG + k * 256 + ((g ^ (k & 15)) * 16));
            const void* src = Bg + (long)k * Ndim + g * 8;
            asm volatile("cp.async.cg.shared.global [%0],[%1],16;\n" :: "r"(dst), "l"(src));
        }
    };

    float acc[4][4][4];
    #pragma unroll
    for (int i = 0; i < 4; ++i)
        #pragma unroll
        for (int j = 0; j < 4; ++j){ acc[i][j][0]=0.f; acc[i][j][1]=0.f; acc[i][j][2]=0.f; acc[i][j][3]=0.f; }

    load_stage(0, 0);
    asm volatile("cp.async.commit_group;\n");
    if (Kt > 1) load_stage(1, 1);
    asm volatile("cp.async.commit_group;\n");

    for (int kt = 0; kt < Kt; ++kt){
        asm volatile("cp.async.wait_group 1;\n");
        __syncthreads();
        int st = kt % KST;
        if (kt + 2 < Kt) load_stage(kt + 2, (kt + 2) % KST);
        asm volatile("cp.async.commit_group;\n");

        char* cA = sA + st * ASTG;
        char* cB = sB + st * BSTG;
        #pragma unroll
        for (int kk = 0; kk < 4; ++kk){
            uint32_t af[4][4];
            #pragma unroll
            for (int mf = 0; mf < 4; ++mf){
                int r = wm * 64 + mf * 16 + (lane & 15);
                int g = kk * 2 + (lane >> 4);
                uint32_t addr = smem_u32(cA + r * 128 + ((g ^ (r & 7)) * 16));
                asm volatile("ldmatrix.sync.aligned.m8n8.x4.shared.b16 {%0,%1,%2,%3},[%4];\n"
                    : "=r"(af[mf][0]), "=r"(af[mf][1]), "=r"(af[mf][2]), "=r"(af[mf][3]) : "r"(addr));
            }
            uint32_t bfr[4][2];
            #pragma unroll
            for (int n2 = 0; n2 < 2; ++n2){
                int k = kk * 16 + (lane & 15);
                int gn = wn * 4 + n2 * 2 + (lane >> 4);
                uint32_t addr = smem_u32(cB + k * 256 + ((gn ^ (k & 15)) * 16));
                uint32_t r0, r1, r2, r3;
                asm volatile("ldmatrix.sync.aligned.m8n8.x4.trans.shared.b16 {%0,%1,%2,%3},[%4];\n"
                    : "=r"(r0), "=r"(r1), "=r"(r2), "=r"(r3) : "r"(addr));
                bfr[n2*2][0]=r0; bfr[n2*2][1]=r1; bfr[n2*2+1][0]=r2; bfr[n2*2+1][1]=r3;
            }
            #pragma unroll
            for (int mf = 0; mf < 4; ++mf)
                #pragma unroll
                for (int nf = 0; nf < 4; ++nf)
                    asm volatile("mma.sync.aligned.m16n8k16.row.col.f32.bf16.bf16.f32 "
                        "{%0,%1,%2,%3},{%4,%5,%6,%7},{%8,%9},{%0,%1,%2,%3};\n"
                        : "+f"(acc[mf][nf][0]), "+f"(acc[mf][nf][1]),
                          "+f"(acc[mf][nf][2]), "+f"(acc[mf][nf][3])
                        : "r"(af[mf][0]), "r"(af[mf][1]), "r"(af[mf][2]), "r"(af[mf][3]),
                          "r"(bfr[nf][0]), "r"(bfr[nf][1]));
        }
    }

    #pragma unroll
    for (int mf = 0; mf < 4; ++mf)
        #pragma unroll
        for (int nf = 0; nf < 4; ++nf){
            int gm = bm + wm * 64 + mf * 16 + (lane >> 2);
            int cc = bn + wn * 32 + nf * 8 + (lane & 3) * 2;
            float b0 = bias ? bias[cc] : 0.f;
            float b1 = bias ? bias[cc + 1] : 0.f;
            if (colsum){ b0 += 0.5f * colsum[cc]; b1 += 0.5f * colsum[cc + 1]; }
            float v00 = acc[mf][nf][0] + b0, v01 = acc[mf][nf][1] + b1;
            float v10 = acc[mf][nf][2] + b0, v11 = acc[mf][nf][3] + b1;
            if (EPI == 0){
                float* Cp = (float*)C;
                *(float2*)(Cp + (long)gm * Ndim + cc)       = make_float2(v00, v01);
                *(float2*)(Cp + (long)(gm + 8) * Ndim + cc) = make_float2(v10, v11);
            } else {
                v00 = 0.5f * tanhf(0.5f * v00); v01 = 0.5f * tanhf(0.5f * v01);
                v10 = 0.5f * tanhf(0.5f * v10); v11 = 0.5f * tanhf(0.5f * v11);
                __nv_bfloat16* Cp = (__nv_bfloat16*)C;
                __nv_bfloat162 t0; t0.x = __float2bfloat16(v00); t0.y = __float2bfloat16(v01);
                __nv_bfloat162 t1; t1.x = __float2bfloat16(v10); t1.y = __float2bfloat16(v11);
                *(__nv_bfloat162*)(Cp + (long)gm * Ndim + cc)       = t0;
                *(__nv_bfloat162*)(Cp + (long)(gm + 8) * Ndim + cc) = t1;
            }
        }
}

// --------------------- small GEMM (proven path) ------------------------------
// EPI 0: f32 ; 2: relu bf16 ; 3: f32 to C AND plain bf16 to C2.
#define BM 128
#define BK 32
#define STAGES 3

template<int BN, int EPI>
__global__ void __launch_bounds__(256) gemm_bf16(
    const __nv_bfloat16* __restrict__ A, const __nv_bfloat16* __restrict__ B,
    void* __restrict__ C, const float* __restrict__ bias, const float* __restrict__ colsum,
    int Kdim, int Ndim, long aB, long bB, long cB, long biasB,
    __nv_bfloat16* __restrict__ C2)
{
    constexpr int WARPS_N = (BN == 128) ? 4 : 2;
    constexpr int WARPS_M = 8 / WARPS_N;
    constexpr int WMT = BM / WARPS_M;
    constexpr int WNT = BN / WARPS_N;
    constexpr int MF = WMT / 16;
    constexpr int NF = WNT / 8;
    constexpr int APITCH = 80;
    constexpr int ASTAGE = BM * APITCH;
    constexpr int BPITCH = BN * 2;
    constexpr int BSTAGE = BK * BPITCH;
    constexpr int GR = BN / 8;
    constexpr int BROWS = 256 / GR;
    constexpr int BPASSES = BK / BROWS;

    extern __shared__ char smem[];
    char* sA = smem;
    char* sB = smem + STAGES * ASTAGE;

    int z = blockIdx.z;
    A += z * aB; B += z * bB;
    const float* biasp = bias ? bias + z * biasB : nullptr;

    int tid = threadIdx.x, lane = tid & 31, wid = tid >> 5;
    int wm = wid / WARPS_N, wn = wid % WARPS_N;
    int bm = blockIdx.y * BM, bn = blockIdx.x * BN;
    int am = tid >> 2, ag = tid & 3;
    int bkr = tid / GR, bg = tid % GR;
    const int Ktiles = Kdim / BK;

    auto load_stage = [&](int kt, int st){
        const __nv_bfloat16* Ag = A + (long)bm * Kdim + kt * BK;
        #pragma unroll
        for (int p = 0; p < 2; ++p){
            int row = am + p * 64;
            uint32_t dst = smem_u32(sA + st * ASTAGE + row * APITCH + ag * 16);
            const void* src = Ag + (long)row * Kdim + ag * 8;
            asm volatile("cp.async.cg.shared.global [%0],[%1],16;\n" :: "r"(dst), "l"(src));
        }
        const __nv_bfloat16* Bg = B + (long)(kt * BK) * Ndim + bn;
        #pragma unroll
        for (int p = 0; p < BPASSES; ++p){
            int k = bkr + p * BROWS;
            uint32_t dst = smem_u32(sB + st * BSTAGE + k * BPITCH + ((bg ^ (k & 7)) * 16));
            const void* src = Bg + (long)k * Ndim + bg * 8;
            asm volatile("cp.async.cg.shared.global [%0],[%1],16;\n" :: "r"(dst), "l"(src));
        }
    };

    float acc[MF][NF][4];
    #pragma unroll
    for (int i = 0; i < MF; ++i)
        #pragma unroll
        for (int j = 0; j < NF; ++j){ acc[i][j][0]=0.f; acc[i][j][1]=0.f; acc[i][j][2]=0.f; acc[i][j][3]=0.f; }

    load_stage(0, 0);
    asm volatile("cp.async.commit_group;\n");
    if (Ktiles > 1) load_stage(1, 1);
    asm volatile("cp.async.commit_group;\n");

    for (int kt = 0; kt < Ktiles; ++kt){
        asm volatile("cp.async.wait_group 1;\n");
        __syncthreads();
        int st = kt % STAGES;
        if (kt + 2 < Ktiles) load_stage(kt + 2, (kt + 2) % STAGES);
        asm volatile("cp.async.commit_group;\n");

        char* cA = sA + st * ASTAGE;
        char* cB = sB + st * BSTAGE;
        #pragma unroll
        for (int kk = 0; kk < 2; ++kk){
            uint32_t af[MF][4];
            #pragma unroll
            for (int mf = 0; mf < MF; ++mf){
                int r = wm * WMT + mf * 16 + (lane & 15);
                uint32_t addr = smem_u32(cA + r * APITCH + kk * 32 + (lane >> 4) * 16);
                asm volatile("ldmatrix.sync.aligned.m8n8.x4.shared.b16 {%0,%1,%2,%3},[%4];\n"
                    : "=r"(af[mf][0]), "=r"(af[mf][1]), "=r"(af[mf][2]), "=r"(af[mf][3]) : "r"(addr));
            }
            uint32_t bfr[NF][2];
            #pragma unroll
            for (int n2 = 0; n2 < NF/2; ++n2){
                int k = kk * 16 + (lane & 15);
                int gn = (wn * WNT + n2 * 16) / 8 + (lane >> 4);
                uint32_t addr = smem_u32(cB + k * BPITCH + ((gn ^ (k & 7)) * 16));
                uint32_t r0, r1, r2, r3;
                asm volatile("ldmatrix.sync.aligned.m8n8.x4.trans.shared.b16 {%0,%1,%2,%3},[%4];\n"
                    : "=r"(r0), "=r"(r1), "=r"(r2), "=r"(r3) : "r"(addr));
                bfr[n2*2][0]=r0; bfr[n2*2][1]=r1; bfr[n2*2+1][0]=r2; bfr[n2*2+1][1]=r3;
            }
            #pragma unroll
            for (int mf = 0; mf < MF; ++mf)
                #pragma unroll
                for (int nf = 0; nf < NF; ++nf)
                    asm volatile("mma.sync.aligned.m16n8k16.row.col.f32.bf16.bf16.f32 "
                        "{%0,%1,%2,%3},{%4,%5,%6,%7},{%8,%9},{%0,%1,%2,%3};\n"
                        : "+f"(acc[mf][nf][0]), "+f"(acc[mf][nf][1]),
                          "+f"(acc[mf][nf][2]), "+f"(acc[mf][nf][3])
                        : "r"(af[mf][0]), "r"(af[mf][1]), "r"(af[mf][2]), "r"(af[mf][3]),
                          "r"(bfr[nf][0]), "r"(bfr[nf][1]));
        }
    }

    long cz = z * cB;
    #pragma unroll
    for (int mf = 0; mf < MF; ++mf)
        #pragma unroll
        for (int nf = 0; nf < NF; ++nf){
            int gm = bm + wm * WMT + mf * 16 + (lane >> 2);
            int cc = bn + wn * WNT + nf * 8 + (lane & 3) * 2;
            float b0 = biasp ? biasp[cc] : 0.f;
            float b1 = biasp ? biasp[cc + 1] : 0.f;
            if (colsum){ b0 += 0.5f * colsum[cc]; b1 += 0.5f * colsum[cc + 1]; }
            float v00 = acc[mf][nf][0] + b0, v01 = acc[mf][nf][1] + b1;
            float v10 = acc[mf][nf][2] + b0, v11 = acc[mf][nf][3] + b1;
            if (EPI == 0 || EPI == 3){
                float* Cp = (float*)C + cz;
                *(float2*)(Cp + (long)gm * Ndim + cc)       = make_float2(v00, v01);
                *(float2*)(Cp + (long)(gm + 8) * Ndim + cc) = make_float2(v10, v11);
                if (EPI == 3){
                    __nv_bfloat162 t0 = __floats2bfloat162_rn(v00, v01);
                    __nv_bfloat162 t1 = __floats2bfloat162_rn(v10, v11);
                    *(__nv_bfloat162*)(C2 + (long)gm * Ndim + cc)       = t0;
                    *(__nv_bfloat162*)(C2 + (long)(gm + 8) * Ndim + cc) = t1;
                }
            } else {
                v00 = fmaxf(v00, 0.f); v01 = fmaxf(v01, 0.f);
                v10 = fmaxf(v10, 0.f); v11 = fmaxf(v11, 0.f);
                __nv_bfloat16* Cp = (__nv_bfloat16*)C + cz;
                __nv_bfloat162 t0; t0.x = __float2bfloat16(v00); t0.y = __float2bfloat16(v01);
                __nv_bfloat162 t1; t1.x = __float2bfloat16(v10); t1.y = __float2bfloat16(v11);
                *(__nv_bfloat162*)(Cp + (long)gm * Ndim + cc)       = t0;
                *(__nv_bfloat162*)(Cp + (long)(gm + 8) * Ndim + cc) = t1;
            }
        }
}

// ------------------------------ host -----------------------------------------
template<int BN, int EPI>
static void launch_gemm(const __nv_bfloat16* A, const __nv_bfloat16* B, void* C,
                        const float* bias, const float* cs, int K, int N, int batch,
                        long aB, long bB, long cBt, long biasB,
                        __nv_bfloat16* C2 = nullptr){
    constexpr int SMB = STAGES * (BM * 80) + STAGES * (BK * BN * 2);
    cudaFuncSetAttribute(gemm_bf16<BN, EPI>, cudaFuncAttributeMaxDynamicSharedMemorySize, SMB);
    dim3 grid(N / BN, NTOK / BM, batch);
    gemm_bf16<BN, EPI><<<grid, 256, SMB>>>(A, B, C, bias, cs, K, N, aB, bB, cBt, biasB, C2);
}

template<int EPI>
static void launch_k64(const __nv_bfloat16* A, const __nv_bfloat16* B, void* C,
                       const float* bias, const float* cs, int K, int N){
    constexpr int SMB = KST * (KBM * 128) + KST * (KBK * 256);
    cudaFuncSetAttribute(gemm_bk64<EPI>, cudaFuncAttributeMaxDynamicSharedMemorySize, SMB);
    dim3 grid(N / KBN, NTOK / KBM, 1);
    gemm_bk64<EPI><<<grid, 256, SMB>>>(A, B, C, bias, cs, K, N);
}

template<typename T> static T* sym(T* s){ void* p = nullptr; cudaGetSymbolAddress(&p, (const void*)s); return (T*)p; }

extern "C" void kernel_launch(void* const* d_in, const int* in_sizes, int n_in,
                              void* d_out, int out_size){
    (void)in_sizes; (void)n_in; (void)out_size;
    const void*  ids   = d_in[0];
    const float* emb   = (const float*)d_in[1];
    const float* enc_W = (const float*)d_in[2];  const float* enc_b = (const float*)d_in[3];
    const float* s2c_W = (const float*)d_in[4];  const float* s2c_b = (const float*)d_in[5];
    const float* rW1   = (const float*)d_in[6];  const float* rb1   = (const float*)d_in[7];
    const float* rW2   = (const float*)d_in[8];  const float* rb2   = (const float*)d_in[9];
    const float* eW1   = (const float*)d_in[10]; const float* eb1   = (const float*)d_in[11];
    const float* eW2   = (const float*)d_in[12]; const float* eb2   = (const float*)d_in[13];
    const float* c2s_W = (const float*)d_in[14]; const float* c2s_b = (const float*)d_in[15];
    const float* dec_W = (const float*)d_in[16]; const float* dec_b = (const float*)d_in[17];
    const float* out_W = (const float*)d_in[18]; const float* out_b = (const float*)d_in[19];
    float* logits = (float*)d_out;
    float* probs  = logits + (size_t)NTOK * VOCAB;

    __nv_bfloat16 *xbf = sym(g_xbf), *spk = sym(g_spk), *moe = sym(g_moe), *decd = sym(g_decd);
    __nv_bfloat16 *contbf = sym(g_contbf), *eobf = sym(g_eobf), *h1 = sym(g_h1);
    float *cont = sym(g_cont), *eo = sym(g_eo), *wfull = sym(g_wfull);
    __nv_bfloat16 *Wenc = sym(g_Wenc), *Ws2c = sym(g_Ws2c), *We1 = sym(g_We1), *We2 = sym(g_We2);
    __nv_bfloat16 *Wc2s = sym(g_Wc2s), *Wdec = sym(g_Wdec), *Wout = sym(g_Wout);
    float *cs_s2c = sym(g_cs_s2c), *cs_dec = sym(g_cs_dec), *cs_out = sym(g_cs_out);

    // ---- fork a side stream for input-only weight converts (capture-legal
    // fork-join: event on capturing stream -> side waits -> work -> join). ----
    cudaStream_t side;
    cudaStreamCreate(&side);
    cudaEvent_t evRoot, evW12, evLate;
    cudaEventCreateWithFlags(&evRoot, cudaEventDisableTiming);
    cudaEventCreateWithFlags(&evW12,  cudaEventDisableTiming);
    cudaEventCreateWithFlags(&evLate, cudaEventDisableTiming);
    cudaEventRecord(evRoot, 0);
    cudaStreamWaitEvent(side, evRoot, 0);

    // side: expert weights first (needed earliest), then c2s/dec/out converts
    f2b4_kernel<<<(NEXP*MDIM*HEXP/4 + 255)/256, 256, 0, side>>>((const float4*)eW1, (__nv_bfloat162*)We1, NEXP*MDIM*HEXP/4);
    f2b4_kernel<<<(NEXP*HEXP*MDIM/4 + 255)/256, 256, 0, side>>>((const float4*)eW2, (__nv_bfloat162*)We2, NEXP*HEXP*MDIM/4);
    cudaEventRecord(evW12, side);
    f2b4_kernel<<<(MDIM*HDIM/4 + 255)/256, 256, 0, side>>>((const float4*)c2s_W, (__nv_bfloat162*)Wc2s, MDIM*HDIM/4);
    cudaMemsetAsync(cs_dec, 0, DMODEL * sizeof(float), side);
    cudaMemsetAsync(cs_out, 0, VOCAB * sizeof(float), side);
    wconv_cs4_kernel<<<dim3(1, 64), 256, 0, side>>>(dec_W, Wdec, cs_dec, HDIM, DMODEL);
    wconv_cs4_kernel<<<dim3(32, 32), 256, 0, side>>>(out_W, Wout, cs_out, DMODEL, VOCAB);
    cudaEventRecord(evLate, side);

    // main: embedding path + enc/s2c weights (needed immediately)
    detect_kernel<<<1, 256>>>((const unsigned int*)ids);
    gather_kernel<<<NTOK, 256>>>(ids, (const float4*)emb, (__nv_bfloat162*)xbf);
    f2b4_kernel<<<(DMODEL*HDIM/4 + 255)/256, 256>>>((const float4*)enc_W, (__nv_bfloat162*)Wenc, DMODEL*HDIM/4);
    cudaMemsetAsync(cs_s2c, 0, MDIM * sizeof(float));
    wconv_cs4_kernel<<<dim3(1, 64), 256>>>(s2c_W, Ws2c, cs_s2c, HDIM, MDIM);

    // enc: sigmoid-0.5 -> spk (bf16)
    launch_k64<1>(xbf, Wenc, spk, enc_b, nullptr, DMODEL, HDIM);
    // s2c: fp32 cont + bf16 contbf in one pass, +0.5*colsum correction
    launch_gemm<64, 3>(spk, Ws2c, cont, s2c_b, cs_s2c, HDIM, MDIM, 1, 0, 0, 0, 0, contbf);
    router_kernel<<<NTOK/8, 256>>>(cont, rW1, rb1, rW2, rb2, probs, wfull);

    // join 1: expert weights ready
    cudaStreamWaitEvent(0, evW12, 0);
    launch_gemm<128, 2>(contbf, We1, h1, eb1, nullptr, MDIM, HEXP, NEXP,
                        0, (long)MDIM*HEXP, (long)NTOK*HEXP, HEXP);
    launch_gemm<64, 0>(h1, We2, eo, eb2, nullptr, HEXP, MDIM, NEXP,
                       (long)NTOK*HEXP, (long)HEXP*MDIM, (long)NTOK*MDIM, MDIM);
    combine_kernel<<<NTOK*MDIM/256, 256>>>(eo, wfull, eobf);

    // join 2: c2s/dec/out weights ready
    cudaStreamWaitEvent(0, evLate, 0);
    // c2s: sigmoid-0.5 (K=64 -> single main-loop iteration)
    launch_k64<1>(eobf, Wc2s, moe, c2s_b, nullptr, MDIM, HDIM);
    // dec: centered input, sigmoid-0.5
    launch_k64<1>(moe, Wdec, decd, dec_b, cs_dec, HDIM, DMODEL);
    // out: centered input, fp32 logits
    launch_k64<0>(decd, Wout, logits, out_b, cs_out, DMODEL, VOCAB);

    cudaStreamDestroy(side);
    cudaEventDestroy(evRoot);
    cudaEventDestroy(evW12);
    cudaEventDestroy(evLate);
}